// round 15
// baseline (speedup 1.0000x reference)
#include <cuda_runtime.h>
#include <math.h>

// Problem constants (fixed by the reference)
#define NN      1000      // codeword length
#define KK      500       // info bits
#define MM      500       // parity checks
#define NSYM    250       // NN / BPS
#define NITER   5
#define NCW     4000      // BATCH * NUE  (codewords)
#define NROW    250000    // BATCH * NSYM (LMMSE rows)
#define NPE     1500      // P edges (3 per info var, row-major order)
#define NEDGE   2000
#define RSQRT2  0.70710678118654752f

// ---------------- scratch (device globals; no allocation allowed) -----------
__device__ unsigned char g_bits[NN * NCW];           // 4 MB  bits [n][cw]
__device__ float4        g_dem[NROW * 4];            // 16 MB {xr, xi, inv_nv, -}
__device__ float         g_Lch[NN * NCW];            // 16 MB channel LLRs [n][cw]
__device__ float         g_c2v_a[NEDGE * NCW];       // 32 MB c2v ping
__device__ float         g_c2v_b[NEDGE * NCW];       // 32 MB c2v pong
__device__ int           g_coff[MM + 1];             // check CSR offsets
__device__ int           g_cedge[NEDGE];             // edge ids per check (ascending)

// 16-QAM constellation (matches reference POINTS)
__constant__ float2 c_pts[16] = {
    { 0.31622776601683794f,  0.31622776601683794f}, { 0.31622776601683794f,  0.9486832980505138f},
    { 0.9486832980505138f,   0.31622776601683794f}, { 0.9486832980505138f,   0.9486832980505138f},
    { 0.31622776601683794f, -0.31622776601683794f}, { 0.31622776601683794f, -0.9486832980505138f},
    { 0.9486832980505138f,  -0.31622776601683794f}, { 0.9486832980505138f,  -0.9486832980505138f},
    {-0.31622776601683794f,  0.31622776601683794f}, {-0.31622776601683794f,  0.9486832980505138f},
    {-0.9486832980505138f,   0.31622776601683794f}, {-0.9486832980505138f,   0.9486832980505138f},
    {-0.31622776601683794f, -0.31622776601683794f}, {-0.31622776601683794f, -0.9486832980505138f},
    {-0.9486832980505138f,  -0.31622776601683794f}, {-0.9486832980505138f,  -0.9486832980505138f}
};

// ---------------- complex helpers -------------------------------------------
struct C2 { float x, y; };
__device__ __forceinline__ C2 cmul(C2 a, C2 b)  { return { a.x*b.x - a.y*b.y, a.x*b.y + a.y*b.x }; }
__device__ __forceinline__ C2 cmulc(C2 a, C2 b) { return { a.x*b.x + a.y*b.y, a.y*b.x - a.x*b.y }; } // a*conj(b)
__device__ __forceinline__ C2 cadd(C2 a, C2 b)  { return { a.x + b.x, a.y + b.y }; }
__device__ __forceinline__ C2 csub(C2 a, C2 b)  { return { a.x - b.x, a.y - b.y }; }
__device__ __forceinline__ C2 cinv(C2 a) { float s = 1.0f/(a.x*a.x + a.y*a.y); return { a.x*s, -a.y*s }; }

// ---------------- setup: check-side CSR (atomic slots + per-check sort) -----
// Final g_cedge order per check: ascending edge id (== stable scan order),
// identity edge NPE+j naturally last (largest id). Deterministic.
__global__ void setup_kernel(const int* __restrict__ cn) {
    __shared__ int cnt[MM];
    __shared__ int coff[MM + 1];
    __shared__ int cur[MM];
    int t = threadIdx.x;
    for (int i = t; i < MM; i += blockDim.x) cnt[i] = 0;
    __syncthreads();
    for (int e = t; e < NPE; e += blockDim.x) atomicAdd(&cnt[cn[e]], 1);
    __syncthreads();
    if (t == 0) {
        int a = 0;
        for (int j = 0; j < MM; j++) { coff[j] = a; a += cnt[j] + 1; }  // +1 identity edge
        coff[MM] = a;
    }
    __syncthreads();
    for (int i = t; i < MM; i += blockDim.x) cur[i] = coff[i];
    __syncthreads();
    // place P-edges (nondeterministic slot order within a check)
    for (int e = t; e < NPE; e += blockDim.x) {
        int j = cn[e];
        int pos = atomicAdd(&cur[j], 1);
        g_cedge[pos] = e;
    }
    // place identity edge at the reserved last slot
    for (int j = t; j < MM; j += blockDim.x)
        g_cedge[coff[j + 1] - 1] = NPE + j;
    __syncthreads();
    // per-check insertion sort of the P-edge span -> deterministic ascending
    for (int j = t; j < MM; j += blockDim.x) {
        int b0 = coff[j], b1 = coff[j + 1] - 1;     // exclude identity slot
        for (int a = b0 + 1; a < b1; a++) {
            int key = g_cedge[a];
            int q = a - 1;
            while (q >= b0 && g_cedge[q] > key) { g_cedge[q + 1] = g_cedge[q]; q--; }
            g_cedge[q + 1] = key;
        }
    }
    for (int i = t; i <= MM; i += blockDim.x) g_coff[i] = coff[i];
}

// ---------------- bits: copy bf to out + transpose to [n][cw] ---------------
__global__ void bits_kernel(const int* __restrict__ b, float* __restrict__ out) {
    __shared__ unsigned char tile[32][33];
    int i0 = blockIdx.x * 32, cw0 = blockIdx.y * 32;
    int tx = threadIdx.x, ty = threadIdx.y;                // block (32,8)
    for (int yy = ty; yy < 32; yy += 8) {
        int cw = cw0 + yy, i = i0 + tx;
        if (cw < NCW && i < KK) {
            int v = b[cw * KK + i];
            out[cw * KK + i] = (float)v;                   // bf half of output (exact)
            tile[yy][tx] = (unsigned char)v;
        }
    }
    __syncthreads();
    for (int yy = ty; yy < 32; yy += 8) {
        int i = i0 + yy, cw = cw0 + tx;
        if (cw < NCW && i < KK) g_bits[i * NCW + cw] = tile[tx][yy];
    }
}

// ---------------- parity: XOR over check's P-edges (4 cw per thread) --------
__global__ void parity_kernel() {
    int tid = blockIdx.x * blockDim.x + threadIdx.x;       // j*(NCW/4) + cw4
    if (tid >= MM * (NCW / 4)) return;
    int j = tid / (NCW / 4), cw4 = tid % (NCW / 4);
    int b0 = g_coff[j], b1 = g_coff[j + 1] - 1;            // exclude identity edge
    unsigned int acc = 0;
    for (int k = b0; k < b1; k++) {
        int e = g_cedge[k];
        acc ^= *reinterpret_cast<const unsigned int*>(&g_bits[(e / 3) * NCW + cw4 * 4]);
    }
    *reinterpret_cast<unsigned int*>(&g_bits[(KK + j) * NCW + cw4 * 4]) = acc & 0x01010101u;
}

// ---------------- LMMSE detect (map fused in; in-place LU) -----------------
__device__ __forceinline__ void lu_solve(const C2 A[4][4], const C2 dinv[4],
                                         const int piv[4], C2 b[4]) {
#pragma unroll
    for (int k = 0; k < 4; k++) {
        int p = piv[k];
#pragma unroll
        for (int q = 0; q < 4; q++) {
            if (q > k && q == p) { C2 t = b[k]; b[k] = b[q]; b[q] = t; }
        }
    }
#pragma unroll
    for (int k = 0; k < 4; k++) {
#pragma unroll
        for (int rr = 0; rr < 4; rr++)
            if (rr > k) b[rr] = csub(b[rr], cmul(A[rr][k], b[k]));
    }
#pragma unroll
    for (int rr = 3; rr >= 0; rr--) {
        C2 val = b[rr];
#pragma unroll
        for (int q = 0; q < 4; q++)
            if (q > rr) val = csub(val, cmul(A[rr][q], b[q]));
        b[rr] = cmul(val, dinv[rr]);
    }
}

__global__ void lmmse_kernel(const float* __restrict__ h_re, const float* __restrict__ h_im,
                             const float* __restrict__ n_re, const float* __restrict__ n_im,
                             const float* __restrict__ ebno) {
    int r = blockIdx.x * blockDim.x + threadIdx.x;
    if (r >= NROW) return;

    float no  = 1.0f / (exp10f(ebno[0] * 0.1f) * 4.0f * 0.5f);
    float wsc = sqrtf(no * 0.5f);

    int bb = r / NSYM, s = r % NSYM;

    // map fused: 16-QAM symbols for the 4 UEs of this (batch, sym) row
    C2 xs[4];
    {
        int n0 = s * 4;
        uchar4 q0 = *reinterpret_cast<const uchar4*>(&g_bits[ n0      * NCW + bb * 4]);
        uchar4 q1 = *reinterpret_cast<const uchar4*>(&g_bits[(n0 + 1) * NCW + bb * 4]);
        uchar4 q2 = *reinterpret_cast<const uchar4*>(&g_bits[(n0 + 2) * NCW + bb * 4]);
        uchar4 q3 = *reinterpret_cast<const uchar4*>(&g_bits[(n0 + 3) * NCW + bb * 4]);
        float2 p;
        p = c_pts[(q0.x << 3) | (q1.x << 2) | (q2.x << 1) | q3.x]; xs[0] = { p.x, p.y };
        p = c_pts[(q0.y << 3) | (q1.y << 2) | (q2.y << 1) | q3.y]; xs[1] = { p.x, p.y };
        p = c_pts[(q0.z << 3) | (q1.z << 2) | (q2.z << 1) | q3.z]; xs[2] = { p.x, p.y };
        p = c_pts[(q0.w << 3) | (q1.w << 2) | (q2.w << 1) | q3.w]; xs[3] = { p.x, p.y };
    }

    C2 h[4][4];
    const float4* hr4 = reinterpret_cast<const float4*>(h_re + (size_t)r * 16);
    const float4* hi4 = reinterpret_cast<const float4*>(h_im + (size_t)r * 16);
#pragma unroll
    for (int i = 0; i < 4; i++) {
        float4 a = hr4[i], bbv = hi4[i];
        h[i][0] = { a.x * RSQRT2, bbv.x * RSQRT2 };
        h[i][1] = { a.y * RSQRT2, bbv.y * RSQRT2 };
        h[i][2] = { a.z * RSQRT2, bbv.z * RSQRT2 };
        h[i][3] = { a.w * RSQRT2, bbv.w * RSQRT2 };
    }

    // y = h x + w
    C2 y[4];
    {
        float4 nr = reinterpret_cast<const float4*>(n_re)[r];
        float4 ni = reinterpret_cast<const float4*>(n_im)[r];
        float nrv[4] = { nr.x, nr.y, nr.z, nr.w };
        float niv[4] = { ni.x, ni.y, ni.z, ni.w };
#pragma unroll
        for (int i = 0; i < 4; i++) {
            C2 acc = { nrv[i] * wsc, niv[i] * wsc };
#pragma unroll
            for (int j = 0; j < 4; j++)
                acc = cadd(acc, cmul(h[i][j], xs[j]));
            y[i] = acc;
        }
    }

    // A = h h^H + no I  (same accumulation order as before)
    C2 A[4][4];
#pragma unroll
    for (int i = 0; i < 4; i++) {
#pragma unroll
        for (int k = 0; k < 4; k++) {
            C2 a = { (i == k) ? no : 0.0f, 0.0f };
#pragma unroll
            for (int j = 0; j < 4; j++) a = cadd(a, cmulc(h[i][j], h[k][j]));
            A[i][k] = a;
        }
    }

    // In-place LU with partial pivoting (cabs1 = |re|+|im|); f stored in lower.
    int piv[4];
    C2 dinv[4];
#pragma unroll
    for (int k = 0; k < 4; k++) {
        int p = k;
        float best = fabsf(A[k][k].x) + fabsf(A[k][k].y);
#pragma unroll
        for (int q = 0; q < 4; q++) {
            if (q > k) {
                float m = fabsf(A[q][k].x) + fabsf(A[q][k].y);
                if (m > best) { best = m; p = q; }
            }
        }
        piv[k] = p;
#pragma unroll
        for (int q = 0; q < 4; q++) {
            if (q > k && q == p) {
#pragma unroll
                for (int c = 0; c < 4; c++) { C2 t = A[k][c]; A[k][c] = A[q][c]; A[q][c] = t; }
            }
        }
        C2 piv_inv = cinv(A[k][k]);
        dinv[k] = piv_inv;
#pragma unroll
        for (int rr = 0; rr < 4; rr++) {
            if (rr > k) {
                C2 f = cmul(A[rr][k], piv_inv);
                A[rr][k] = f;
#pragma unroll
                for (int c = 0; c < 4; c++)
                    if (c > k) A[rr][c] = csub(A[rr][c], cmul(f, A[k][c]));
            }
        }
    }

    lu_solve(A, dinv, piv, y);

#pragma unroll
    for (int j = 0; j < 4; j++) {
        C2 hc[4];
#pragma unroll
        for (int i = 0; i < 4; i++) hc[i] = h[i][j];
        lu_solve(A, dinv, piv, hc);

        C2 xraw = {0.f, 0.f};
        float d = 0.f;
#pragma unroll
        for (int i = 0; i < 4; i++) {
            xraw = cadd(xraw, cmulc(y[i], h[i][j]));
            C2 gw = cmulc(hc[i], h[i][j]);
            d += gw.x;
        }
        float inv_d = 1.0f / d;
        float xr = xraw.x * inv_d, xi = xraw.y * inv_d;
        float noe = fmaxf(inv_d - 1.0f, 1e-12f);
        float inv_nv = 1.0f / noe;
        g_dem[r * 4 + j] = make_float4(xr, xi, inv_nv, 0.0f);
    }
}

// ---------------- max-log demap (2 cw per thread; identical expressions) ----
__global__ void demap_kernel() {
    int tid = blockIdx.x * blockDim.x + threadIdx.x;       // s*(NCW/2) + cw2
    if (tid >= NSYM * (NCW / 2)) return;
    int s = tid / (NCW / 2), cw = (tid % (NCW / 2)) * 2;
    int bb = cw >> 2, u = cw & 3;
    float4 dm0 = g_dem[(bb * NSYM + s) * 4 + u];
    float4 dm1 = g_dem[(bb * NSYM + s) * 4 + u + 1];

    float llr0[4], llr1[4];
    {
        float xr = dm0.x, xi = dm0.y, inv_nv = dm0.z;
        float best0[4] = {3.4e38f, 3.4e38f, 3.4e38f, 3.4e38f};
        float best1[4] = {3.4e38f, 3.4e38f, 3.4e38f, 3.4e38f};
#pragma unroll
        for (int p = 0; p < 16; p++) {
            float dr = xr - c_pts[p].x, di = xi - c_pts[p].y;
            float d2 = dr * dr + di * di;
#pragma unroll
            for (int k = 0; k < 4; k++) {
                if ((p >> (3 - k)) & 1) best1[k] = fminf(best1[k], d2);
                else                    best0[k] = fminf(best0[k], d2);
            }
        }
#pragma unroll
        for (int k = 0; k < 4; k++) llr0[k] = (best1[k] - best0[k]) * inv_nv;
    }
    {
        float xr = dm1.x, xi = dm1.y, inv_nv = dm1.z;
        float best0[4] = {3.4e38f, 3.4e38f, 3.4e38f, 3.4e38f};
        float best1[4] = {3.4e38f, 3.4e38f, 3.4e38f, 3.4e38f};
#pragma unroll
        for (int p = 0; p < 16; p++) {
            float dr = xr - c_pts[p].x, di = xi - c_pts[p].y;
            float d2 = dr * dr + di * di;
#pragma unroll
            for (int k = 0; k < 4; k++) {
                if ((p >> (3 - k)) & 1) best1[k] = fminf(best1[k], d2);
                else                    best0[k] = fminf(best0[k], d2);
            }
        }
#pragma unroll
        for (int k = 0; k < 4; k++) llr1[k] = (best1[k] - best0[k]) * inv_nv;
    }
#pragma unroll
    for (int k = 0; k < 4; k++)
        *reinterpret_cast<float2*>(&g_Lch[(size_t)(s * 4 + k) * NCW + cw]) =
            make_float2(llr0[k], llr1[k]);
}

// ---------------- fused LDPC iteration (float4; degree-templated) -----------
__device__ __forceinline__ float tanh_cl(float m) {
    float a = fminf(fmaxf(0.5f * m, -9.9f), 9.9f);
    float t = tanhf(a);
    return (t >= 0.0f) ? fmaxf(t, 1e-7f) : fminf(t, -1e-7f);
}
__device__ __forceinline__ float4 tanh_cl4(float4 m) {
    return { tanh_cl(m.x), tanh_cl(m.y), tanh_cl(m.z), tanh_cl(m.w) };
}
__device__ __forceinline__ float4 ld4(const float* p) {
    return *reinterpret_cast<const float4*>(p);
}

// m_vc for edge e (4 lanes); identical per-lane fp order to scalar version
__device__ __forceinline__ float4 edge_msg4(const float* __restrict__ o, int e, int c) {
    if (e < NPE) {
        int v = e / 3, r0 = v * 3;
        float4 a0 = ld4(&o[r0 * NCW + c]);
        float4 a1 = ld4(&o[(r0 + 1) * NCW + c]);
        float4 a2 = ld4(&o[(r0 + 2) * NCW + c]);
        float4 L  = ld4(&g_Lch[v * NCW + c]);
        float4 vt = { ((L.x + a0.x) + a1.x) + a2.x, ((L.y + a0.y) + a1.y) + a2.y,
                      ((L.z + a0.z) + a1.z) + a2.z, ((L.w + a0.w) + a1.w) + a2.w };
        int sl = e - r0;
        float4 me = (sl == 0) ? a0 : ((sl == 1) ? a1 : a2);
        return { vt.x - me.x, vt.y - me.y, vt.z - me.z, vt.w - me.w };
    } else {
        int v = KK + (e - NPE);
        float4 cc = ld4(&o[e * NCW + c]);
        float4 L  = ld4(&g_Lch[v * NCW + c]);
        return { (L.x + cc.x) - cc.x, (L.y + cc.y) - cc.y,
                 (L.z + cc.z) - cc.z, (L.w + cc.w) - cc.w };   // keep (L+c)-c rounding
    }
}

// it0: c2v==0 -> m_vc == Lch[v] bit-exactly (L+0+0+0-0 == L; Lch never -0)
__device__ __forceinline__ float4 edge_msg4_it0(int e, int c) {
    int v = (e < NPE) ? (e / 3) : (KK + (e - NPE));
    return ld4(&g_Lch[v * NCW + c]);
}

__device__ __forceinline__ void write_msgs4(float* __restrict__ n, int e, int c,
                                            float4 prod, float4 t) {
    float rx = prod.x / t.x, ry = prod.y / t.y, rz = prod.z / t.z, rw = prod.w / t.w;
    rx = fminf(fmaxf(rx, -0.999999f), 0.999999f);
    ry = fminf(fmaxf(ry, -0.999999f), 0.999999f);
    rz = fminf(fmaxf(rz, -0.999999f), 0.999999f);
    rw = fminf(fmaxf(rw, -0.999999f), 0.999999f);
    *reinterpret_cast<float4*>(&n[e * NCW + c]) =
        make_float4(2.0f * atanhf(rx), 2.0f * atanhf(ry),
                    2.0f * atanhf(rz), 2.0f * atanhf(rw));
}

// Fixed-degree check body; IT0 selects the implicit-zero-c2v message path.
template <int DEG, int IT0>
__device__ __forceinline__ void check_body(const float* __restrict__ o,
                                           float* __restrict__ n, int b0, int c) {
    int   e[DEG];
    float4 t[DEG];
    float4 prod = { 1.0f, 1.0f, 1.0f, 1.0f };
#pragma unroll
    for (int k = 0; k < DEG; k++) {
        e[k] = g_cedge[b0 + k];
        float4 tt = tanh_cl4(IT0 ? edge_msg4_it0(e[k], c) : edge_msg4(o, e[k], c));
        t[k] = tt;
        prod.x *= tt.x; prod.y *= tt.y; prod.z *= tt.z; prod.w *= tt.w;
    }
#pragma unroll
    for (int k = 0; k < DEG; k++)
        write_msgs4(n, e[k], c, prod, t[k]);
}

// Generic fallback (any degree; identical math, recompute in pass 2)
template <int IT0>
__device__ __forceinline__ void check_body_gen(const float* __restrict__ o,
                                               float* __restrict__ n,
                                               int b0, int b1, int c) {
    float4 prod = { 1.0f, 1.0f, 1.0f, 1.0f };
    for (int k = b0; k < b1; k++) {
        float4 tt = tanh_cl4(IT0 ? edge_msg4_it0(g_cedge[k], c) : edge_msg4(o, g_cedge[k], c));
        prod.x *= tt.x; prod.y *= tt.y; prod.z *= tt.z; prod.w *= tt.w;
    }
    for (int k = b0; k < b1; k++) {
        int e = g_cedge[k];
        float4 tt = tanh_cl4(IT0 ? edge_msg4_it0(e, c) : edge_msg4(o, e, c));
        write_msgs4(n, e, c, prod, tt);
    }
}

template <int IT0>
__device__ __forceinline__ void check_dispatch(const float* __restrict__ o,
                                               float* __restrict__ n, int tid) {
    int j = tid / (NCW / 4), c = (tid % (NCW / 4)) * 4;
    int b0 = g_coff[j], b1 = g_coff[j + 1];
    switch (b1 - b0) {
        case 1:  check_body<1,  IT0>(o, n, b0, c); break;
        case 2:  check_body<2,  IT0>(o, n, b0, c); break;
        case 3:  check_body<3,  IT0>(o, n, b0, c); break;
        case 4:  check_body<4,  IT0>(o, n, b0, c); break;
        case 5:  check_body<5,  IT0>(o, n, b0, c); break;
        case 6:  check_body<6,  IT0>(o, n, b0, c); break;
        case 7:  check_body<7,  IT0>(o, n, b0, c); break;
        case 8:  check_body<8,  IT0>(o, n, b0, c); break;
        case 9:  check_body<9,  IT0>(o, n, b0, c); break;
        case 10: check_body<10, IT0>(o, n, b0, c); break;
        default: check_body_gen<IT0>(o, n, b0, b1, c); break;
    }
}

__global__ void ldpc_iter0_kernel() {
    int tid = blockIdx.x * blockDim.x + threadIdx.x;
    if (tid >= MM * (NCW / 4)) return;
    check_dispatch<1>(nullptr, g_c2v_b, tid);
}

// DIR=0: read g_c2v_a, write g_c2v_b.  DIR=1: read g_c2v_b, write g_c2v_a.
template <int DIR>
__global__ void ldpc_iter_kernel() {
    int tid = blockIdx.x * blockDim.x + threadIdx.x;
    if (tid >= MM * (NCW / 4)) return;
    const float* o = DIR ? g_c2v_b : g_c2v_a;
    float* n       = DIR ? g_c2v_a : g_c2v_b;
    check_dispatch<0>(o, n, tid);
}

// ---------------- final hard decision + transposed write --------------------
// Reads g_c2v_b (final messages after it0->b, b->a, a->b, b->a, a->b)
__global__ void bhat_kernel(float* __restrict__ out) {
    __shared__ float tile[32][33];
    int i0 = blockIdx.x * 32, cw0 = blockIdx.y * 32;
    int tx = threadIdx.x, ty = threadIdx.y;                    // block (32,8)
    for (int yy = ty; yy < 32; yy += 8) {
        int i = i0 + yy, cw = cw0 + tx;
        if (cw < NCW && i < KK) {
            int r0 = i * 3;
            float s = g_Lch[i * NCW + cw];
            s += g_c2v_b[r0 * NCW + cw];
            s += g_c2v_b[(r0 + 1) * NCW + cw];
            s += g_c2v_b[(r0 + 2) * NCW + cw];
            tile[yy][tx] = (s < 0.0f) ? 1.0f : 0.0f;
        }
    }
    __syncthreads();
    for (int yy = ty; yy < 32; yy += 8) {
        int cw = cw0 + yy, i = i0 + tx;
        if (cw < NCW && i < KK)
            out[(size_t)NCW * KK + (size_t)cw * KK + i] = tile[tx][yy];
    }
}

// ---------------- launch ----------------------------------------------------
extern "C" void kernel_launch(void* const* d_in, const int* in_sizes, int n_in,
                              void* d_out, int out_size) {
    int base = n_in - 9;
    const float* ebno = (const float*)d_in[base + 0];
    const int*   b    = (const int*)  d_in[base + 1];
    const int*   cn   = (const int*)  d_in[base + 3];
    const float* h_re = (const float*)d_in[base + 5];
    const float* h_im = (const float*)d_in[base + 6];
    const float* n_re = (const float*)d_in[base + 7];
    const float* n_im = (const float*)d_in[base + 8];
    float* out = (float*)d_out;

    const int T = 256;

    setup_kernel<<<1, 512>>>(cn);

    dim3 tb(32, 8);
    bits_kernel<<<dim3((KK + 31) / 32, NCW / 32), tb>>>(b, out);
    parity_kernel<<<(MM * (NCW / 4) + T - 1) / T, T>>>();
    lmmse_kernel<<<(NROW + T - 1) / T, T>>>(h_re, h_im, n_re, n_im, ebno);
    demap_kernel<<<(NSYM * (NCW / 2) + T - 1) / T, T>>>();

    // 5 iterations: specialized it0 (implicit-zero c2v) then 4 ping-pongs
    const int G4 = (MM * (NCW / 4) + T - 1) / T;
    ldpc_iter0_kernel<<<G4, T>>>();    //      -> b
    ldpc_iter_kernel<1><<<G4, T>>>();  // b -> a
    ldpc_iter_kernel<0><<<G4, T>>>();  // a -> b
    ldpc_iter_kernel<1><<<G4, T>>>();  // b -> a
    ldpc_iter_kernel<0><<<G4, T>>>();  // a -> b  (final in g_c2v_b)

    bhat_kernel<<<dim3((KK + 31) / 32, NCW / 32), tb>>>(out);
}

// round 16
// speedup vs baseline: 1.2888x; 1.2888x over previous
#include <cuda_runtime.h>
#include <math.h>

// Problem constants (fixed by the reference)
#define NN      1000      // codeword length
#define KK      500       // info bits
#define MM      500       // parity checks
#define NSYM    250       // NN / BPS
#define NITER   5
#define NCW     4000      // BATCH * NUE  (codewords)
#define NROW    250000    // BATCH * NSYM (LMMSE rows)
#define NPE     1500      // P edges (3 per info var, row-major order)
#define NEDGE   2000
#define MAXDEG  10        // max check degree handled in registers
#define RSQRT2  0.70710678118654752f

// ---------------- scratch (device globals; no allocation allowed) -----------
__device__ unsigned char g_bits[NN * NCW];           // 4 MB  bits [n][cw]
__device__ float4        g_dem[NROW * 4];            // 16 MB {xr, xi, inv_nv, -}
__device__ float         g_Lch[NN * NCW];            // 16 MB channel LLRs [n][cw]
__device__ float         g_c2v_a[NEDGE * NCW];       // 32 MB c2v ping
__device__ float         g_c2v_b[NEDGE * NCW];       // 32 MB c2v pong
__device__ int           g_coff[MM + 1];             // check CSR offsets
__device__ int           g_cedge[NEDGE];             // edge ids per check (ascending)

// 16-QAM constellation (matches reference POINTS)
__constant__ float2 c_pts[16] = {
    { 0.31622776601683794f,  0.31622776601683794f}, { 0.31622776601683794f,  0.9486832980505138f},
    { 0.9486832980505138f,   0.31622776601683794f}, { 0.9486832980505138f,   0.9486832980505138f},
    { 0.31622776601683794f, -0.31622776601683794f}, { 0.31622776601683794f, -0.9486832980505138f},
    { 0.9486832980505138f,  -0.31622776601683794f}, { 0.9486832980505138f,  -0.9486832980505138f},
    {-0.31622776601683794f,  0.31622776601683794f}, {-0.31622776601683794f,  0.9486832980505138f},
    {-0.9486832980505138f,   0.31622776601683794f}, {-0.9486832980505138f,   0.9486832980505138f},
    {-0.31622776601683794f, -0.31622776601683794f}, {-0.31622776601683794f, -0.9486832980505138f},
    {-0.9486832980505138f,  -0.31622776601683794f}, {-0.9486832980505138f,  -0.9486832980505138f}
};

// ---------------- complex helpers -------------------------------------------
struct C2 { float x, y; };
__device__ __forceinline__ C2 cmul(C2 a, C2 b)  { return { a.x*b.x - a.y*b.y, a.x*b.y + a.y*b.x }; }
__device__ __forceinline__ C2 cmulc(C2 a, C2 b) { return { a.x*b.x + a.y*b.y, a.y*b.x - a.x*b.y }; } // a*conj(b)
__device__ __forceinline__ C2 cadd(C2 a, C2 b)  { return { a.x + b.x, a.y + b.y }; }
__device__ __forceinline__ C2 csub(C2 a, C2 b)  { return { a.x - b.x, a.y - b.y }; }
__device__ __forceinline__ C2 cinv(C2 a) { float s = 1.0f/(a.x*a.x + a.y*a.y); return { a.x*s, -a.y*s }; }

// ---------------- setup: check-side CSR (atomic slots + per-check sort) -----
// Final g_cedge order per check: ascending edge id (== stable scan order),
// identity edge NPE+j naturally last (largest id). Deterministic.
__global__ void setup_kernel(const int* __restrict__ cn) {
    __shared__ int cnt[MM];
    __shared__ int coff[MM + 1];
    __shared__ int cur[MM];
    int t = threadIdx.x;
    for (int i = t; i < MM; i += blockDim.x) cnt[i] = 0;
    __syncthreads();
    for (int e = t; e < NPE; e += blockDim.x) atomicAdd(&cnt[cn[e]], 1);
    __syncthreads();
    if (t == 0) {
        int a = 0;
        for (int j = 0; j < MM; j++) { coff[j] = a; a += cnt[j] + 1; }  // +1 identity edge
        coff[MM] = a;
    }
    __syncthreads();
    for (int i = t; i < MM; i += blockDim.x) cur[i] = coff[i];
    __syncthreads();
    // place P-edges (nondeterministic slot order within a check)
    for (int e = t; e < NPE; e += blockDim.x) {
        int j = cn[e];
        int pos = atomicAdd(&cur[j], 1);
        g_cedge[pos] = e;
    }
    // place identity edge at the reserved last slot
    for (int j = t; j < MM; j += blockDim.x)
        g_cedge[coff[j + 1] - 1] = NPE + j;
    __syncthreads();
    // per-check insertion sort of the P-edge span -> deterministic ascending
    for (int j = t; j < MM; j += blockDim.x) {
        int b0 = coff[j], b1 = coff[j + 1] - 1;     // exclude identity slot
        for (int a = b0 + 1; a < b1; a++) {
            int key = g_cedge[a];
            int q = a - 1;
            while (q >= b0 && g_cedge[q] > key) { g_cedge[q + 1] = g_cedge[q]; q--; }
            g_cedge[q + 1] = key;
        }
    }
    for (int i = t; i <= MM; i += blockDim.x) g_coff[i] = coff[i];
}

// ---------------- bits: copy bf to out + transpose to [n][cw] ---------------
__global__ void bits_kernel(const int* __restrict__ b, float* __restrict__ out) {
    __shared__ unsigned char tile[32][33];
    int i0 = blockIdx.x * 32, cw0 = blockIdx.y * 32;
    int tx = threadIdx.x, ty = threadIdx.y;                // block (32,8)
    for (int yy = ty; yy < 32; yy += 8) {
        int cw = cw0 + yy, i = i0 + tx;
        if (cw < NCW && i < KK) {
            int v = b[cw * KK + i];
            out[cw * KK + i] = (float)v;                   // bf half of output (exact)
            tile[yy][tx] = (unsigned char)v;
        }
    }
    __syncthreads();
    for (int yy = ty; yy < 32; yy += 8) {
        int i = i0 + yy, cw = cw0 + tx;
        if (cw < NCW && i < KK) g_bits[i * NCW + cw] = tile[tx][yy];
    }
}

// ---------------- parity: XOR over check's P-edges (4 cw per thread) --------
__global__ void parity_kernel() {
    int tid = blockIdx.x * blockDim.x + threadIdx.x;       // j*(NCW/4) + cw4
    if (tid >= MM * (NCW / 4)) return;
    int j = tid / (NCW / 4), cw4 = tid % (NCW / 4);
    int b0 = g_coff[j], b1 = g_coff[j + 1] - 1;            // exclude identity edge
    unsigned int acc = 0;
    for (int k = b0; k < b1; k++) {
        int e = g_cedge[k];
        acc ^= *reinterpret_cast<const unsigned int*>(&g_bits[(e / 3) * NCW + cw4 * 4]);
    }
    *reinterpret_cast<unsigned int*>(&g_bits[(KK + j) * NCW + cw4 * 4]) = acc & 0x01010101u;
}

// ---------------- LMMSE detect (map fused in; in-place LU) -----------------
__device__ __forceinline__ void lu_solve(const C2 A[4][4], const C2 dinv[4],
                                         const int piv[4], C2 b[4]) {
#pragma unroll
    for (int k = 0; k < 4; k++) {
        int p = piv[k];
#pragma unroll
        for (int q = 0; q < 4; q++) {
            if (q > k && q == p) { C2 t = b[k]; b[k] = b[q]; b[q] = t; }
        }
    }
#pragma unroll
    for (int k = 0; k < 4; k++) {
#pragma unroll
        for (int rr = 0; rr < 4; rr++)
            if (rr > k) b[rr] = csub(b[rr], cmul(A[rr][k], b[k]));
    }
#pragma unroll
    for (int rr = 3; rr >= 0; rr--) {
        C2 val = b[rr];
#pragma unroll
        for (int q = 0; q < 4; q++)
            if (q > rr) val = csub(val, cmul(A[rr][q], b[q]));
        b[rr] = cmul(val, dinv[rr]);
    }
}

__global__ void lmmse_kernel(const float* __restrict__ h_re, const float* __restrict__ h_im,
                             const float* __restrict__ n_re, const float* __restrict__ n_im,
                             const float* __restrict__ ebno) {
    int r = blockIdx.x * blockDim.x + threadIdx.x;
    if (r >= NROW) return;

    float no  = 1.0f / (exp10f(ebno[0] * 0.1f) * 4.0f * 0.5f);
    float wsc = sqrtf(no * 0.5f);

    int bb = r / NSYM, s = r % NSYM;

    // map fused: 16-QAM symbols for the 4 UEs of this (batch, sym) row
    C2 xs[4];
    {
        int n0 = s * 4;
        uchar4 q0 = *reinterpret_cast<const uchar4*>(&g_bits[ n0      * NCW + bb * 4]);
        uchar4 q1 = *reinterpret_cast<const uchar4*>(&g_bits[(n0 + 1) * NCW + bb * 4]);
        uchar4 q2 = *reinterpret_cast<const uchar4*>(&g_bits[(n0 + 2) * NCW + bb * 4]);
        uchar4 q3 = *reinterpret_cast<const uchar4*>(&g_bits[(n0 + 3) * NCW + bb * 4]);
        float2 p;
        p = c_pts[(q0.x << 3) | (q1.x << 2) | (q2.x << 1) | q3.x]; xs[0] = { p.x, p.y };
        p = c_pts[(q0.y << 3) | (q1.y << 2) | (q2.y << 1) | q3.y]; xs[1] = { p.x, p.y };
        p = c_pts[(q0.z << 3) | (q1.z << 2) | (q2.z << 1) | q3.z]; xs[2] = { p.x, p.y };
        p = c_pts[(q0.w << 3) | (q1.w << 2) | (q2.w << 1) | q3.w]; xs[3] = { p.x, p.y };
    }

    C2 h[4][4];
    const float4* hr4 = reinterpret_cast<const float4*>(h_re + (size_t)r * 16);
    const float4* hi4 = reinterpret_cast<const float4*>(h_im + (size_t)r * 16);
#pragma unroll
    for (int i = 0; i < 4; i++) {
        float4 a = hr4[i], bbv = hi4[i];
        h[i][0] = { a.x * RSQRT2, bbv.x * RSQRT2 };
        h[i][1] = { a.y * RSQRT2, bbv.y * RSQRT2 };
        h[i][2] = { a.z * RSQRT2, bbv.z * RSQRT2 };
        h[i][3] = { a.w * RSQRT2, bbv.w * RSQRT2 };
    }

    // y = h x + w
    C2 y[4];
    {
        float4 nr = reinterpret_cast<const float4*>(n_re)[r];
        float4 ni = reinterpret_cast<const float4*>(n_im)[r];
        float nrv[4] = { nr.x, nr.y, nr.z, nr.w };
        float niv[4] = { ni.x, ni.y, ni.z, ni.w };
#pragma unroll
        for (int i = 0; i < 4; i++) {
            C2 acc = { nrv[i] * wsc, niv[i] * wsc };
#pragma unroll
            for (int j = 0; j < 4; j++)
                acc = cadd(acc, cmul(h[i][j], xs[j]));
            y[i] = acc;
        }
    }

    // A = h h^H + no I  (same accumulation order as before)
    C2 A[4][4];
#pragma unroll
    for (int i = 0; i < 4; i++) {
#pragma unroll
        for (int k = 0; k < 4; k++) {
            C2 a = { (i == k) ? no : 0.0f, 0.0f };
#pragma unroll
            for (int j = 0; j < 4; j++) a = cadd(a, cmulc(h[i][j], h[k][j]));
            A[i][k] = a;
        }
    }

    // In-place LU with partial pivoting (cabs1 = |re|+|im|); f stored in lower.
    int piv[4];
    C2 dinv[4];
#pragma unroll
    for (int k = 0; k < 4; k++) {
        int p = k;
        float best = fabsf(A[k][k].x) + fabsf(A[k][k].y);
#pragma unroll
        for (int q = 0; q < 4; q++) {
            if (q > k) {
                float m = fabsf(A[q][k].x) + fabsf(A[q][k].y);
                if (m > best) { best = m; p = q; }
            }
        }
        piv[k] = p;
#pragma unroll
        for (int q = 0; q < 4; q++) {
            if (q > k && q == p) {
#pragma unroll
                for (int c = 0; c < 4; c++) { C2 t = A[k][c]; A[k][c] = A[q][c]; A[q][c] = t; }
            }
        }
        C2 piv_inv = cinv(A[k][k]);
        dinv[k] = piv_inv;
#pragma unroll
        for (int rr = 0; rr < 4; rr++) {
            if (rr > k) {
                C2 f = cmul(A[rr][k], piv_inv);
                A[rr][k] = f;
#pragma unroll
                for (int c = 0; c < 4; c++)
                    if (c > k) A[rr][c] = csub(A[rr][c], cmul(f, A[k][c]));
            }
        }
    }

    lu_solve(A, dinv, piv, y);

#pragma unroll
    for (int j = 0; j < 4; j++) {
        C2 hc[4];
#pragma unroll
        for (int i = 0; i < 4; i++) hc[i] = h[i][j];
        lu_solve(A, dinv, piv, hc);

        C2 xraw = {0.f, 0.f};
        float d = 0.f;
#pragma unroll
        for (int i = 0; i < 4; i++) {
            xraw = cadd(xraw, cmulc(y[i], h[i][j]));
            C2 gw = cmulc(hc[i], h[i][j]);
            d += gw.x;
        }
        float inv_d = 1.0f / d;
        float xr = xraw.x * inv_d, xi = xraw.y * inv_d;
        float noe = fmaxf(inv_d - 1.0f, 1e-12f);
        float inv_nv = 1.0f / noe;
        g_dem[r * 4 + j] = make_float4(xr, xi, inv_nv, 0.0f);
    }
}

// ---------------- max-log demap (2 cw per thread; identical expressions) ----
__global__ void demap_kernel() {
    int tid = blockIdx.x * blockDim.x + threadIdx.x;       // s*(NCW/2) + cw2
    if (tid >= NSYM * (NCW / 2)) return;
    int s = tid / (NCW / 2), cw = (tid % (NCW / 2)) * 2;
    int bb = cw >> 2, u = cw & 3;
    float4 dm0 = g_dem[(bb * NSYM + s) * 4 + u];
    float4 dm1 = g_dem[(bb * NSYM + s) * 4 + u + 1];

    float llr0[4], llr1[4];
    {
        float xr = dm0.x, xi = dm0.y, inv_nv = dm0.z;
        float best0[4] = {3.4e38f, 3.4e38f, 3.4e38f, 3.4e38f};
        float best1[4] = {3.4e38f, 3.4e38f, 3.4e38f, 3.4e38f};
#pragma unroll
        for (int p = 0; p < 16; p++) {
            float dr = xr - c_pts[p].x, di = xi - c_pts[p].y;
            float d2 = dr * dr + di * di;
#pragma unroll
            for (int k = 0; k < 4; k++) {
                if ((p >> (3 - k)) & 1) best1[k] = fminf(best1[k], d2);
                else                    best0[k] = fminf(best0[k], d2);
            }
        }
#pragma unroll
        for (int k = 0; k < 4; k++) llr0[k] = (best1[k] - best0[k]) * inv_nv;
    }
    {
        float xr = dm1.x, xi = dm1.y, inv_nv = dm1.z;
        float best0[4] = {3.4e38f, 3.4e38f, 3.4e38f, 3.4e38f};
        float best1[4] = {3.4e38f, 3.4e38f, 3.4e38f, 3.4e38f};
#pragma unroll
        for (int p = 0; p < 16; p++) {
            float dr = xr - c_pts[p].x, di = xi - c_pts[p].y;
            float d2 = dr * dr + di * di;
#pragma unroll
            for (int k = 0; k < 4; k++) {
                if ((p >> (3 - k)) & 1) best1[k] = fminf(best1[k], d2);
                else                    best0[k] = fminf(best0[k], d2);
            }
        }
#pragma unroll
        for (int k = 0; k < 4; k++) llr1[k] = (best1[k] - best0[k]) * inv_nv;
    }
#pragma unroll
    for (int k = 0; k < 4; k++)
        *reinterpret_cast<float2*>(&g_Lch[(size_t)(s * 4 + k) * NCW + cw]) =
            make_float2(llr0[k], llr1[k]);
}

// ---------------- fused LDPC iteration (float4: 4 cw per thread) ------------
__device__ __forceinline__ float tanh_cl(float m) {
    float a = fminf(fmaxf(0.5f * m, -9.9f), 9.9f);
    float t = tanhf(a);
    return (t >= 0.0f) ? fmaxf(t, 1e-7f) : fminf(t, -1e-7f);
}
__device__ __forceinline__ float4 tanh_cl4(float4 m) {
    return { tanh_cl(m.x), tanh_cl(m.y), tanh_cl(m.z), tanh_cl(m.w) };
}
__device__ __forceinline__ float4 ld4(const float* p) {
    return *reinterpret_cast<const float4*>(p);
}

// m_vc for edge e (4 lanes); identical per-lane fp order to scalar version
__device__ __forceinline__ float4 edge_msg4(const float* __restrict__ o, int e, int c) {
    if (e < NPE) {
        int v = e / 3, r0 = v * 3;
        float4 a0 = ld4(&o[r0 * NCW + c]);
        float4 a1 = ld4(&o[(r0 + 1) * NCW + c]);
        float4 a2 = ld4(&o[(r0 + 2) * NCW + c]);
        float4 L  = ld4(&g_Lch[v * NCW + c]);
        float4 vt = { ((L.x + a0.x) + a1.x) + a2.x, ((L.y + a0.y) + a1.y) + a2.y,
                      ((L.z + a0.z) + a1.z) + a2.z, ((L.w + a0.w) + a1.w) + a2.w };
        int sl = e - r0;
        float4 me = (sl == 0) ? a0 : ((sl == 1) ? a1 : a2);
        return { vt.x - me.x, vt.y - me.y, vt.z - me.z, vt.w - me.w };
    } else {
        int v = KK + (e - NPE);
        float4 cc = ld4(&o[e * NCW + c]);
        float4 L  = ld4(&g_Lch[v * NCW + c]);
        return { (L.x + cc.x) - cc.x, (L.y + cc.y) - cc.y,
                 (L.z + cc.z) - cc.z, (L.w + cc.w) - cc.w };   // keep (L+c)-c rounding
    }
}

__device__ __forceinline__ void write_msgs4(float* __restrict__ n, int e, int c,
                                            float4 prod, float4 t) {
    float rx = prod.x / t.x, ry = prod.y / t.y, rz = prod.z / t.z, rw = prod.w / t.w;
    rx = fminf(fmaxf(rx, -0.999999f), 0.999999f);
    ry = fminf(fmaxf(ry, -0.999999f), 0.999999f);
    rz = fminf(fmaxf(rz, -0.999999f), 0.999999f);
    rw = fminf(fmaxf(rw, -0.999999f), 0.999999f);
    *reinterpret_cast<float4*>(&n[e * NCW + c]) =
        make_float4(2.0f * atanhf(rx), 2.0f * atanhf(ry),
                    2.0f * atanhf(rz), 2.0f * atanhf(rw));
}

// Iteration 0: c2v == 0 everywhere, so m_vc == Lch[v] bit-exactly
// (L+0+0+0-0 == L for all finite L; Lch is never -0).  No c2v reads needed.
__global__ void ldpc_iter0_kernel() {
    float* __restrict__ n = g_c2v_b;
    int tid = blockIdx.x * blockDim.x + threadIdx.x;           // j*(NCW/4) + cw4
    if (tid >= MM * (NCW / 4)) return;
    int j = tid / (NCW / 4), c = (tid % (NCW / 4)) * 4;
    int b0 = g_coff[j], b1 = g_coff[j + 1];
    int deg = b1 - b0;

    float4 t[MAXDEG];
    float4 prod = { 1.0f, 1.0f, 1.0f, 1.0f };
#pragma unroll
    for (int k = 0; k < MAXDEG; k++) {
        if (k < deg) {
            int e = g_cedge[b0 + k];
            int v = (e < NPE) ? (e / 3) : (KK + (e - NPE));
            float4 tt = tanh_cl4(ld4(&g_Lch[v * NCW + c]));
            t[k] = tt;
            prod.x *= tt.x; prod.y *= tt.y; prod.z *= tt.z; prod.w *= tt.w;
        }
    }
    for (int k = MAXDEG; k < deg; k++) {                       // rare fallback tail
        int e = g_cedge[b0 + k];
        int v = (e < NPE) ? (e / 3) : (KK + (e - NPE));
        float4 tt = tanh_cl4(ld4(&g_Lch[v * NCW + c]));
        prod.x *= tt.x; prod.y *= tt.y; prod.z *= tt.z; prod.w *= tt.w;
    }
#pragma unroll
    for (int k = 0; k < MAXDEG; k++) {
        if (k < deg) write_msgs4(n, g_cedge[b0 + k], c, prod, t[k]);
    }
    for (int k = MAXDEG; k < deg; k++) {
        int e = g_cedge[b0 + k];
        int v = (e < NPE) ? (e / 3) : (KK + (e - NPE));
        float4 tt = tanh_cl4(ld4(&g_Lch[v * NCW + c]));
        write_msgs4(n, e, c, prod, tt);
    }
}

// DIR=0: read g_c2v_a, write g_c2v_b.  DIR=1: read g_c2v_b, write g_c2v_a.
template <int DIR>
__global__ void ldpc_iter_kernel() {
    const float* __restrict__ o = DIR ? g_c2v_b : g_c2v_a;
    float* __restrict__ n       = DIR ? g_c2v_a : g_c2v_b;
    int tid = blockIdx.x * blockDim.x + threadIdx.x;           // j*(NCW/4) + cw4
    if (tid >= MM * (NCW / 4)) return;
    int j = tid / (NCW / 4), c = (tid % (NCW / 4)) * 4;
    int b0 = g_coff[j], b1 = g_coff[j + 1];
    int deg = b1 - b0;

    if (deg <= MAXDEG) {
        float4 t[MAXDEG];
        float4 prod = { 1.0f, 1.0f, 1.0f, 1.0f };
#pragma unroll
        for (int k = 0; k < MAXDEG; k++) {
            if (k < deg) {
                float4 tt = tanh_cl4(edge_msg4(o, g_cedge[b0 + k], c));
                t[k] = tt;
                prod.x *= tt.x; prod.y *= tt.y; prod.z *= tt.z; prod.w *= tt.w;
            }
        }
#pragma unroll
        for (int k = 0; k < MAXDEG; k++) {
            if (k < deg) write_msgs4(n, g_cedge[b0 + k], c, prod, t[k]);
        }
    } else {
        // fallback (degree beyond register cache; identical math, recompute)
        float4 prod = { 1.0f, 1.0f, 1.0f, 1.0f };
        for (int k = b0; k < b1; k++) {
            float4 tt = tanh_cl4(edge_msg4(o, g_cedge[k], c));
            prod.x *= tt.x; prod.y *= tt.y; prod.z *= tt.z; prod.w *= tt.w;
        }
        for (int k = b0; k < b1; k++) {
            int e = g_cedge[k];
            float4 tt = tanh_cl4(edge_msg4(o, e, c));
            write_msgs4(n, e, c, prod, tt);
        }
    }
}

// ---------------- final hard decision + transposed write --------------------
// Reads g_c2v_b (final messages after it0->b, b->a, a->b, b->a, a->b)
__global__ void bhat_kernel(float* __restrict__ out) {
    __shared__ float tile[32][33];
    int i0 = blockIdx.x * 32, cw0 = blockIdx.y * 32;
    int tx = threadIdx.x, ty = threadIdx.y;                    // block (32,8)
    for (int yy = ty; yy < 32; yy += 8) {
        int i = i0 + yy, cw = cw0 + tx;
        if (cw < NCW && i < KK) {
            int r0 = i * 3;
            float s = g_Lch[i * NCW + cw];
            s += g_c2v_b[r0 * NCW + cw];
            s += g_c2v_b[(r0 + 1) * NCW + cw];
            s += g_c2v_b[(r0 + 2) * NCW + cw];
            tile[yy][tx] = (s < 0.0f) ? 1.0f : 0.0f;
        }
    }
    __syncthreads();
    for (int yy = ty; yy < 32; yy += 8) {
        int cw = cw0 + yy, i = i0 + tx;
        if (cw < NCW && i < KK)
            out[(size_t)NCW * KK + (size_t)cw * KK + i] = tile[tx][yy];
    }
}

// ---------------- launch ----------------------------------------------------
extern "C" void kernel_launch(void* const* d_in, const int* in_sizes, int n_in,
                              void* d_out, int out_size) {
    int base = n_in - 9;
    const float* ebno = (const float*)d_in[base + 0];
    const int*   b    = (const int*)  d_in[base + 1];
    const int*   cn   = (const int*)  d_in[base + 3];
    const float* h_re = (const float*)d_in[base + 5];
    const float* h_im = (const float*)d_in[base + 6];
    const float* n_re = (const float*)d_in[base + 7];
    const float* n_im = (const float*)d_in[base + 8];
    float* out = (float*)d_out;

    const int T = 256;

    setup_kernel<<<1, 512>>>(cn);

    dim3 tb(32, 8);
    bits_kernel<<<dim3((KK + 31) / 32, NCW / 32), tb>>>(b, out);
    parity_kernel<<<(MM * (NCW / 4) + T - 1) / T, T>>>();
    lmmse_kernel<<<(NROW + T - 1) / T, T>>>(h_re, h_im, n_re, n_im, ebno);
    demap_kernel<<<(NSYM * (NCW / 2) + T - 1) / T, T>>>();

    // 5 iterations: specialized it0 (implicit-zero c2v) then 4 ping-pongs
    const int G4 = (MM * (NCW / 4) + T - 1) / T;
    ldpc_iter0_kernel<<<G4, T>>>();    //      -> b
    ldpc_iter_kernel<1><<<G4, T>>>();  // b -> a
    ldpc_iter_kernel<0><<<G4, T>>>();  // a -> b
    ldpc_iter_kernel<1><<<G4, T>>>();  // b -> a
    ldpc_iter_kernel<0><<<G4, T>>>();  // a -> b  (final in g_c2v_b)

    bhat_kernel<<<dim3((KK + 31) / 32, NCW / 32), tb>>>(out);
}